// round 12
// baseline (speedup 1.0000x reference)
#include <cuda_runtime.h>
#include <math.h>

#define B_ 4096
#define C_ 50
#define E_ 128
#define M_ 200000
#define F_ 512
#define DK_ 11.313708498984760f

// ---------------- scratch (device globals; no allocation allowed) ----------------
__device__ float g_sim[C_ * B_];          // sim[c*B+b]
__device__ float g_colsum[C_];            // Z_c = sum_b exp(sim[b,c])
__device__ float g_t0[E_];
__device__ float g_t0norm;
__device__ float g_proto[E_];             // SUM of attended (scale by 1/B at use)
__device__ float g_cos_sum;
__device__ float g_simm[M_];
__device__ unsigned g_qkey[M_];           // flipped key of expf(s - mx)
__device__ unsigned g_maxkey;
__device__ float g_Z1;                    // sum exp(s - mx1), for exact scatter w1
__device__ float g_S1, g_S2;              // sum exp(s), sum exp(-s/DK)
__device__ unsigned g_hist[4][256];       // qkey radix (descending)
__device__ unsigned g_ihist[2][512];      // index radix among ties (ascending, 9-bit)
__device__ unsigned g_prefix;
__device__ int g_krem;
__device__ unsigned g_Lkey;               // boundary q-level key
__device__ unsigned g_iprefix;            // pass0: bin b0; pass1: final cut index
__device__ int g_ikrem;
__device__ unsigned g_done[8];            // last-block tickets
__device__ int g_nflag;
__device__ int g_list[1024];
__device__ float g_mem[E_], g_negmem[E_]; // unnormalized U, V sums

// ---------------- helpers ----------------
__device__ __forceinline__ unsigned flipkey(float f) {
    unsigned u = __float_as_uint(f);
    return (u & 0x80000000u) ? ~u : (u | 0x80000000u);
}
__device__ __forceinline__ float unflip(unsigned k) {
    unsigned u = (k & 0x80000000u) ? (k & 0x7FFFFFFFu) : ~k;
    return __uint_as_float(u);
}
__device__ __forceinline__ float warp_sum(float v) {
#pragma unroll
    for (int o = 16; o; o >>= 1) v += __shfl_xor_sync(0xffffffffu, v, o);
    return v;
}
__device__ __forceinline__ float logsig(float x) {
    return (x >= 0.f) ? -log1pf(expf(-x)) : x - log1pf(expf(x));
}

// ---------------- kernels ----------------
__global__ void k_init(const int* __restrict__ target, const float* __restrict__ Wt) {
    int tid = threadIdx.x;  // 256 threads
    if (tid < E_) { g_proto[tid] = 0.f; g_mem[tid] = 0.f; g_negmem[tid] = 0.f; }
    if (tid < C_) g_colsum[tid] = 0.f;
#pragma unroll
    for (int p = 0; p < 4; p++) g_hist[p][tid] = 0u;
#pragma unroll
    for (int p = 0; p < 2; p++) { g_ihist[p][tid] = 0u; g_ihist[p][tid + 256] = 0u; }
    if (tid < 8) g_done[tid] = 0u;
    if (tid == 0) {
        g_cos_sum = 0.f; g_maxkey = 0u;
        g_Z1 = 0.f; g_S1 = 0.f; g_S2 = 0.f; g_prefix = 0u; g_krem = F_;
        g_iprefix = 0u; g_ikrem = 0; g_nflag = 0;
    }
    int ti = target[0];
    float v = 0.f;
    if (tid < E_) { v = Wt[(long)ti * E_ + tid]; g_t0[tid] = v; }
    __shared__ float sm[256];
    sm[tid] = v * v;
    __syncthreads();
    for (int s = 128; s; s >>= 1) { if (tid < s) sm[tid] += sm[tid + s]; __syncthreads(); }
    if (tid == 0) g_t0norm = sqrtf(sm[0]);
}

// batched gather + dot for k_sim; lane0 also accumulates exp into smem Z bins
template<int N>
__device__ __forceinline__ void sim_chunk(const int* __restrict__ cr, int c0,
                                          const float* __restrict__ Wc,
                                          int lane, int b, float4 t4, float* s_z) {
    float4 x[N];
#pragma unroll
    for (int j = 0; j < N; j++) {
        int ci = __ldg(cr + c0 + j);
        x[j] = ((const float4*)(Wc + (long)ci * E_))[lane];
    }
#pragma unroll
    for (int j = 0; j < N; j++) {
        float p = t4.x * x[j].x + t4.y * x[j].y + t4.z * x[j].z + t4.w * x[j].w;
        p = warp_sum(p);
        if (lane == 0) {
            g_sim[(c0 + j) * B_ + b] = p;
            atomicAdd(&s_z[c0 + j], expf(p));
        }
    }
}

// sim[b,c]: 2 warps per b (25 c's each), MLP=10; fused column Z accumulation
__global__ void k_sim(const int* __restrict__ target, const int* __restrict__ contex,
                      const float* __restrict__ Wt, const float* __restrict__ Wc) {
    __shared__ float s_z[C_];
    int tid = threadIdx.x;
    if (tid < C_) s_z[tid] = 0.f;
    __syncthreads();
    int wl = tid >> 5, lane = tid & 31;
    int gw = blockIdx.x * 8 + wl;          // 8192 warps
    int b = gw >> 1, h = gw & 1;
    int ti = __ldg(target + b);
    float4 t4 = ((const float4*)(Wt + (long)ti * E_))[lane];
    const int* cr = contex + b * C_;
    int c0 = h * 25;
    sim_chunk<10>(cr, c0, Wc, lane, b, t4, s_z);
    sim_chunk<10>(cr, c0 + 10, Wc, lane, b, t4, s_z);
    sim_chunk<5>(cr, c0 + 20, Wc, lane, b, t4, s_z);
    __syncthreads();
    if (tid < C_ && s_z[tid] != 0.f) atomicAdd(&g_colsum[tid], s_z[tid]);
}

template<int N>
__device__ __forceinline__ void att_chunk(const int* __restrict__ cr, int c0,
                                          const float* __restrict__ Wc,
                                          int lane, int b, const float* s_inv,
                                          float& ax, float& ay, float& az, float& aw) {
    float4 x[N]; float sc[N];
#pragma unroll
    for (int j = 0; j < N; j++) {
        int ci = __ldg(cr + c0 + j);
        x[j] = ((const float4*)(Wc + (long)ci * E_))[lane];
    }
#pragma unroll
    for (int j = 0; j < N; j++)
        sc[j] = expf(g_sim[(c0 + j) * B_ + b]) * s_inv[c0 + j];
#pragma unroll
    for (int j = 0; j < N; j++) {
        ax += sc[j] * x[j].x; ay += sc[j] * x[j].y;
        az += sc[j] * x[j].z; aw += sc[j] * x[j].w;
    }
}

// attended[b]: 2 warps per b, pairwise combine; accumulate proto & cos
__global__ void k_attend(const int* __restrict__ contex, const float* __restrict__ Wc) {
    __shared__ float s_inv[C_];
    __shared__ float4 s_part[8][32];
    __shared__ float s_acc[E_];
    __shared__ float s_cos;
    int tid = threadIdx.x;
    if (tid < C_) s_inv[tid] = 1.0f / (g_colsum[tid] * DK_);
    if (tid < E_) s_acc[tid] = 0.f;
    if (tid == 0) s_cos = 0.f;
    __syncthreads();
    int wl = tid >> 5, lane = tid & 31;
    int gw = blockIdx.x * 8 + wl;          // 8192 warps
    int b = gw >> 1, h = gw & 1;
    const int* cr = contex + b * C_;
    float ax = 0, ay = 0, az = 0, aw = 0;
    int c0 = h * 25;
    att_chunk<10>(cr, c0, Wc, lane, b, s_inv, ax, ay, az, aw);
    att_chunk<10>(cr, c0 + 10, Wc, lane, b, s_inv, ax, ay, az, aw);
    att_chunk<5>(cr, c0 + 20, Wc, lane, b, s_inv, ax, ay, az, aw);
    s_part[wl][lane] = make_float4(ax, ay, az, aw);
    __syncthreads();
    if ((wl & 1) == 0) {
        float4 p1 = s_part[wl][lane], p2 = s_part[wl + 1][lane];
        ax = p1.x + p2.x; ay = p1.y + p2.y; az = p1.z + p2.z; aw = p1.w + p2.w;
        float4 t4 = ((const float4*)g_t0)[lane];
        float d = ax * t4.x + ay * t4.y + az * t4.z + aw * t4.w;
        float q = ax * ax + ay * ay + az * az + aw * aw;
        d = warp_sum(d); q = warp_sum(q);
        if (lane == 0) {
            float cosb = d / (fmaxf(sqrtf(q), 1e-8f) * fmaxf(g_t0norm, 1e-8f));
            atomicAdd(&s_cos, cosb);
        }
        atomicAdd(&s_acc[lane * 4 + 0], ax);
        atomicAdd(&s_acc[lane * 4 + 1], ay);
        atomicAdd(&s_acc[lane * 4 + 2], az);
        atomicAdd(&s_acc[lane * 4 + 3], aw);
    }
    __syncthreads();
    if (tid < E_) atomicAdd(&g_proto[tid], s_acc[tid]);
    if (tid == 0) atomicAdd(&g_cos_sum, s_cos);
}

// sim_m + fused unnormalized mem/neg accumulation.
// U = sum exp(s_m)*pm[m], V = sum exp(-s_m/DK)*pm[m], S1/S2 scalar sums.
// grid-resident: 444 blocks, grid-stride over 8-row chunks (atomics stay cheap).
__global__ void __launch_bounds__(256) k_simm(const float* __restrict__ pm) {
    __shared__ float4 s_proto4[32];
    __shared__ float s_U[E_], s_V[E_];
    __shared__ float s_S[2];
    __shared__ unsigned s_kmax[8];
    int tid = threadIdx.x, lane = tid & 31, wl = tid >> 5;
    if (tid < 32) {
        float inv = 1.0f / (float)B_;
        float4 p = ((const float4*)g_proto)[tid];
        s_proto4[tid] = make_float4(p.x * inv, p.y * inv, p.z * inv, p.w * inv);
    }
    if (tid < E_) { s_U[tid] = 0.f; s_V[tid] = 0.f; }
    if (tid < 2) s_S[tid] = 0.f;
    __syncthreads();
    float4 p = s_proto4[lane];
    float4 U = make_float4(0, 0, 0, 0), V = make_float4(0, 0, 0, 0);
    float S1 = 0.f, S2 = 0.f;
    unsigned kmax = 0u;
    const int nchunk = M_ / 8;             // 25000
    int cstride = gridDim.x * 8;
    for (int chunk = blockIdx.x * 8 + wl; chunk < nchunk; chunk += cstride) {
        int w = chunk * 8;
        float4 x[8]; float d[8];
#pragma unroll
        for (int r = 0; r < 8; r++) {
            x[r] = ((const float4*)(pm + (long)(w + r) * E_))[lane];
            d[r] = x[r].x * p.x + x[r].y * p.y + x[r].z * p.z + x[r].w * p.w;
        }
#pragma unroll
        for (int r = 0; r < 8; r++) d[r] = warp_sum(d[r]);
        if (lane == 0) {
#pragma unroll
            for (int r = 0; r < 8; r++) {
                g_simm[w + r] = d[r];
                kmax = max(kmax, flipkey(d[r]));
            }
        }
#pragma unroll
        for (int r = 0; r < 8; r++) {
            float e1 = expf(d[r]);
            float e2 = expf(-d[r] / DK_);
            U.x += e1 * x[r].x; U.y += e1 * x[r].y; U.z += e1 * x[r].z; U.w += e1 * x[r].w;
            V.x += e2 * x[r].x; V.y += e2 * x[r].y; V.z += e2 * x[r].z; V.w += e2 * x[r].w;
            if (lane == 0) { S1 += e1; S2 += e2; }
        }
    }
    atomicAdd(&s_U[lane * 4 + 0], U.x); atomicAdd(&s_U[lane * 4 + 1], U.y);
    atomicAdd(&s_U[lane * 4 + 2], U.z); atomicAdd(&s_U[lane * 4 + 3], U.w);
    atomicAdd(&s_V[lane * 4 + 0], V.x); atomicAdd(&s_V[lane * 4 + 1], V.y);
    atomicAdd(&s_V[lane * 4 + 2], V.z); atomicAdd(&s_V[lane * 4 + 3], V.w);
    if (lane == 0) { atomicAdd(&s_S[0], S1); atomicAdd(&s_S[1], S2); s_kmax[wl] = kmax; }
    __syncthreads();
    if (tid < E_) { atomicAdd(&g_mem[tid], s_U[tid]); atomicAdd(&g_negmem[tid], s_V[tid]); }
    if (tid == 0) {
        atomicAdd(&g_S1, s_S[0]); atomicAdd(&g_S2, s_S[1]);
        unsigned kx = s_kmax[0];
        for (int i = 1; i < 8; i++) kx = max(kx, s_kmax[i]);
        atomicMax(&g_maxkey, kx);
    }
}

// Z1 + qkey materialization + qkey radix pass-0 hist + fused scan (last block)
__global__ void k_expsum() {
    __shared__ unsigned h[256];
    __shared__ float s1[8];
    __shared__ bool s_last;
    int tid = threadIdx.x;
    h[tid] = 0u;
    __syncthreads();
    float mx1 = unflip(g_maxkey);
    float z1 = 0.f;
    int idx = blockIdx.x * blockDim.x + tid, stride = gridDim.x * blockDim.x;
    for (int i = idx; i < M_; i += stride) {
        float s = g_simm[i];
        float q = expf(s - mx1);
        unsigned key = flipkey(q);
        g_qkey[i] = key;
        atomicAdd(&h[key >> 24], 1u);
        z1 += q;
    }
    z1 = warp_sum(z1);
    int wl = tid >> 5, lane = tid & 31;
    if (lane == 0) s1[wl] = z1;
    __syncthreads();
    if (tid == 0) {
        float a = 0;
        for (int i = 0; i < 8; i++) a += s1[i];
        atomicAdd(&g_Z1, a);
    }
    if (h[tid]) atomicAdd(&g_hist[0][tid], h[tid]);
    __threadfence();
    if (tid == 0) s_last = (atomicAdd(&g_done[0], 1u) == gridDim.x - 1);
    __syncthreads();
    if (!s_last) return;
    __threadfence();
    h[tid] = g_hist[0][tid];
    __syncthreads();
    if (tid == 0) {
        unsigned cum = 0; int krem = g_krem;
        for (int bin = 255; bin >= 0; bin--) {
            unsigned hh = h[bin];
            if (cum + hh >= (unsigned)krem) {
                g_prefix = (unsigned)bin; g_krem = krem - (int)cum;
                break;
            }
            cum += hh;
        }
    }
}

// qkey radix passes 1..3, fused scan (last block)
__global__ void k_qhist(int pass, int shift, int slot) {
    __shared__ unsigned h[256];
    __shared__ bool s_last;
    int tid = threadIdx.x;
    h[tid] = 0u; __syncthreads();
    unsigned pref = g_prefix;
    int idx = blockIdx.x * blockDim.x + tid, stride = gridDim.x * blockDim.x;
    for (int i = idx; i < M_; i += stride) {
        unsigned key = g_qkey[i];
        if ((key >> (shift + 8)) == pref) atomicAdd(&h[(key >> shift) & 255u], 1u);
    }
    __syncthreads();
    if (h[tid]) atomicAdd(&g_hist[pass][tid], h[tid]);
    __threadfence();
    if (tid == 0) s_last = (atomicAdd(&g_done[slot], 1u) == gridDim.x - 1);
    __syncthreads();
    if (!s_last) return;
    __threadfence();
    h[tid] = g_hist[pass][tid];
    __syncthreads();
    if (tid == 0) {
        unsigned cum = 0; int krem = g_krem;
        for (int bin = 255; bin >= 0; bin--) {
            unsigned hh = h[bin];
            if (cum + hh >= (unsigned)krem) {
                g_prefix = (pref << 8) | (unsigned)bin;
                g_krem = krem - (int)cum;
                if (pass == 3) { g_Lkey = (pref << 8) | (unsigned)bin; g_ikrem = krem - (int)cum; }
                break;
            }
            cum += hh;
        }
    }
}

// ascending index-select among ties (2 passes of 9 bits; indices < 2^18), fused scan
__global__ void k_ihist(int pass, int slot) {
    __shared__ unsigned h[512];
    __shared__ bool s_last;
    int tid = threadIdx.x;
    h[tid] = 0u; h[tid + 256] = 0u;
    __syncthreads();
    unsigned L = g_Lkey;
    unsigned b0 = g_iprefix;
    int idx = blockIdx.x * blockDim.x + tid, stride = gridDim.x * blockDim.x;
    for (int i = idx; i < M_; i += stride) {
        if (g_qkey[i] != L) continue;
        unsigned u = (unsigned)i;
        if (pass == 0) atomicAdd(&h[u >> 9], 1u);
        else if ((u >> 9) == b0) atomicAdd(&h[u & 511u], 1u);
    }
    __syncthreads();
    if (h[tid]) atomicAdd(&g_ihist[pass][tid], h[tid]);
    if (h[tid + 256]) atomicAdd(&g_ihist[pass][tid + 256], h[tid + 256]);
    __threadfence();
    if (tid == 0) s_last = (atomicAdd(&g_done[slot], 1u) == gridDim.x - 1);
    __syncthreads();
    if (!s_last) return;
    __threadfence();
    h[tid] = g_ihist[pass][tid];
    h[tid + 256] = g_ihist[pass][tid + 256];
    __syncthreads();
    if (tid == 0) {
        unsigned cum = 0; int krem = g_ikrem;
        for (int bin = 0; bin < 512; bin++) {
            unsigned hh = h[bin];
            if (cum + hh >= (unsigned)krem) {
                if (pass == 0) { g_iprefix = (unsigned)bin; g_ikrem = krem - (int)cum; }
                else g_iprefix = (b0 << 9) | (unsigned)bin;   // final cut index
                break;
            }
            cum += hh;
        }
    }
}

// build the flagged-row list (set identical to reference top-512)
__global__ void k_flagscan() {
    unsigned L = g_Lkey, cut = g_iprefix;
    int idx = blockIdx.x * blockDim.x + threadIdx.x, stride = gridDim.x * blockDim.x;
    for (int i = idx; i < M_; i += stride) {
        unsigned key = g_qkey[i];
        if (key > L || (key == L && (unsigned)i <= cut)) {
            int p = atomicAdd(&g_nflag, 1);
            if (p < 1024) g_list[p] = i;
        }
    }
}

// rewrite the 512 updated rows (copy of all rows already done by memcpy)
__global__ void k_scatter(const float* __restrict__ pm, float* __restrict__ out,
                          int mem_off, const int* __restrict__ repe, int has_repe) {
    int rep = has_repe ? repe[0] : 1;
    if (!rep) return;
    int tid = threadIdx.x, lane = tid & 31, wl = tid >> 5;
    int gw = blockIdx.x * 8 + wl;          // 64 blocks * 8 = 512 warps
    int n = g_nflag; if (n > 1024) n = 1024;
    if (gw >= n) return;
    int m = g_list[gw];
    float mx1 = unflip(g_maxkey);
    float s = g_simm[m];
    float q = expf(s - mx1);
    float w1 = q / g_Z1 / DK_;             // exact reference score_m[m]
    float inv = 1.0f / (float)B_;
    float4 p = ((const float4*)g_proto)[lane];
    float4 pr = make_float4(p.x * inv, p.y * inv, p.z * inv, p.w * inv);
    float4 v = ((const float4*)(pm + (long)m * E_))[lane];
    float4 o;
    o.x = v.x + w1 * pr.x; o.y = v.y + w1 * pr.y;
    o.z = v.z + w1 * pr.z; o.w = v.w + w1 * pr.w;
    float ss = o.x * o.x + o.y * o.y + o.z * o.z + o.w * o.w;
    ss = warp_sum(ss);
    float inv2 = 1.0f / fmaxf(sqrtf(ss), 1e-12f);
    float* wp = out + mem_off + (long)m * E_ + lane * 4;
    wp[0] = o.x * inv2; wp[1] = o.y * inv2; wp[2] = o.z * inv2; wp[3] = o.w * inv2;
}

__global__ void k_final(float* __restrict__ out, int mem_off) {
    int tid = threadIdx.x;  // 128 threads
    float p = g_proto[tid] * (1.0f / (float)B_);
    float mm = g_mem[tid] / (g_S1 * DK_);       // mem_contex
    float nn = g_negmem[tid] / g_S2;            // neg_mem_contex
    float t = g_t0[tid];
    float v[6] = { p * t, p * p, mm * t, mm * mm, nn * t, nn * nn };
#pragma unroll
    for (int k = 0; k < 6; k++)
#pragma unroll
        for (int o = 16; o; o >>= 1) v[k] += __shfl_xor_sync(0xffffffffu, v[k], o);
    __shared__ float sm[4][6];
    int w = tid >> 5, l = tid & 31;
    if (l == 0) for (int k = 0; k < 6; k++) sm[w][k] = v[k];
    __syncthreads();
    if (tid == 0) {
        float r[6];
        for (int k = 0; k < 6; k++) r[k] = sm[0][k] + sm[1][k] + sm[2][k] + sm[3][k];
        float tn = fmaxf(g_t0norm, 1e-8f);
        float cosP = r[0] / (fmaxf(sqrtf(r[1]), 1e-8f) * tn);
        float cosM = r[2] / (fmaxf(sqrtf(r[3]), 1e-8f) * tn);
        float cosN = r[4] / (fmaxf(sqrtf(r[5]), 1e-8f) * tn);
        float conte = (g_cos_sum + cosP + cosM) / (float)(B_ + 2);
        float negl = -cosN;
        float loss = logsig(conte) + logsig(negl);
        if (mem_off > 0) out[0] = -loss;
    }
}

// ---------------- launch ----------------
extern "C" void kernel_launch(void* const* d_in, const int* in_sizes, int n_in,
                              void* d_out, int out_size) {
    const int* target = (const int*)d_in[0];
    const int* contex = (const int*)d_in[1];
    const float* Wt = (const float*)d_in[2];
    const float* Wc = (const float*)d_in[3];
    const float* pm = (const float*)d_in[4];
    const int* repe = (n_in > 5) ? (const int*)d_in[5] : nullptr;
    float* out = (float*)d_out;
    int mem_off = out_size - M_ * E_;
    if (mem_off < 0) mem_off = 0;

    k_init<<<1, 256>>>(target, Wt);
    // bulk copy of proto_memory into the output (untouched rows); D2D async is capture-legal
    cudaMemcpyAsync(out + mem_off, pm, (size_t)M_ * E_ * sizeof(float),
                    cudaMemcpyDeviceToDevice);
    k_sim<<<1024, 256>>>(target, contex, Wt, Wc);
    k_attend<<<1024, 256>>>(contex, Wc);
    k_simm<<<444, 256>>>(pm);
    k_expsum<<<256, 256>>>();          // qkey pass 0 hist + scan (slot 0)
    k_qhist<<<256, 256>>>(1, 16, 1);
    k_qhist<<<256, 256>>>(2, 8, 2);
    k_qhist<<<256, 256>>>(3, 0, 3);    // also sets Lkey / ikrem
    k_ihist<<<256, 256>>>(0, 4);
    k_ihist<<<256, 256>>>(1, 5);       // sets final cut index
    k_flagscan<<<256, 256>>>();
    k_scatter<<<64, 256>>>(pm, out, mem_off, repe, repe != nullptr);
    k_final<<<1, E_>>>(out, mem_off);
}

// round 13
// speedup vs baseline: 1.1795x; 1.1795x over previous
#include <cuda_runtime.h>
#include <math.h>

#define B_ 4096
#define C_ 50
#define E_ 128
#define M_ 200000
#define F_ 512
#define DK_ 11.313708498984760f

// ---------------- scratch (device globals; no allocation allowed) ----------------
__device__ float g_sim[C_ * B_];          // sim[c*B+b]
__device__ float g_colsum[C_];            // Z_c = sum_b exp(sim[b,c])  (no max-sub; math-equal)
__device__ float g_t0[E_];
__device__ float g_t0norm;
__device__ float g_proto[E_];             // SUM of attended (scale by 1/B at use)
__device__ float g_cos_sum;
__device__ float g_simm[M_];
__device__ unsigned g_qkey[M_];           // flipped key of expf(s - mx)
__device__ unsigned g_maxkey, g_minkey;
__device__ float g_Z1, g_Z2;
__device__ unsigned g_hist[4][256];       // qkey radix (descending)
__device__ unsigned g_ihist[2][512];      // index radix among ties (ascending, 9-bit)
__device__ unsigned g_prefix;
__device__ int g_krem;
__device__ unsigned g_Lkey;               // boundary q-level key
__device__ unsigned g_iprefix;            // pass0: bin b0; pass1: final cut index
__device__ int g_ikrem;
__device__ unsigned g_done[8];            // last-block tickets
__device__ float g_mem[E_], g_negmem[E_];

// ---------------- helpers ----------------
__device__ __forceinline__ unsigned flipkey(float f) {
    unsigned u = __float_as_uint(f);
    return (u & 0x80000000u) ? ~u : (u | 0x80000000u);
}
__device__ __forceinline__ float unflip(unsigned k) {
    unsigned u = (k & 0x80000000u) ? (k & 0x7FFFFFFFu) : ~k;
    return __uint_as_float(u);
}
__device__ __forceinline__ float warp_sum(float v) {
#pragma unroll
    for (int o = 16; o; o >>= 1) v += __shfl_xor_sync(0xffffffffu, v, o);
    return v;
}
__device__ __forceinline__ float logsig(float x) {
    return (x >= 0.f) ? -log1pf(expf(-x)) : x - log1pf(expf(x));
}

// ---------------- kernels ----------------
__global__ void k_init(const int* __restrict__ target, const float* __restrict__ Wt) {
    int tid = threadIdx.x;  // 256 threads
    if (tid < E_) { g_proto[tid] = 0.f; g_mem[tid] = 0.f; g_negmem[tid] = 0.f; }
    if (tid < C_) g_colsum[tid] = 0.f;
#pragma unroll
    for (int p = 0; p < 4; p++) g_hist[p][tid] = 0u;
#pragma unroll
    for (int p = 0; p < 2; p++) { g_ihist[p][tid] = 0u; g_ihist[p][tid + 256] = 0u; }
    if (tid < 8) g_done[tid] = 0u;
    if (tid == 0) {
        g_cos_sum = 0.f; g_maxkey = 0u; g_minkey = 0xFFFFFFFFu;
        g_Z1 = 0.f; g_Z2 = 0.f; g_prefix = 0u; g_krem = F_;
        g_iprefix = 0u; g_ikrem = 0;
    }
    int ti = target[0];
    float v = 0.f;
    if (tid < E_) { v = Wt[(long)ti * E_ + tid]; g_t0[tid] = v; }
    __shared__ float sm[256];
    sm[tid] = v * v;
    __syncthreads();
    for (int s = 128; s; s >>= 1) { if (tid < s) sm[tid] += sm[tid + s]; __syncthreads(); }
    if (tid == 0) g_t0norm = sqrtf(sm[0]);
}

// batched gather + dot for k_sim; lane0 also accumulates exp into smem Z bins
template<int N>
__device__ __forceinline__ void sim_chunk(const int* __restrict__ cr, int c0,
                                          const float* __restrict__ Wc,
                                          int lane, int b, float4 t4, float* s_z) {
    float4 x[N];
#pragma unroll
    for (int j = 0; j < N; j++) {
        int ci = __ldg(cr + c0 + j);
        x[j] = ((const float4*)(Wc + (long)ci * E_))[lane];
    }
#pragma unroll
    for (int j = 0; j < N; j++) {
        float p = t4.x * x[j].x + t4.y * x[j].y + t4.z * x[j].z + t4.w * x[j].w;
        p = warp_sum(p);
        if (lane == 0) {
            g_sim[(c0 + j) * B_ + b] = p;
            atomicAdd(&s_z[c0 + j], expf(p));
        }
    }
}

// sim[b,c]: 2 warps per b (25 c's each), MLP=10; fused column Z accumulation
__global__ void k_sim(const int* __restrict__ target, const int* __restrict__ contex,
                      const float* __restrict__ Wt, const float* __restrict__ Wc) {
    __shared__ float s_z[C_];
    int tid = threadIdx.x;
    if (tid < C_) s_z[tid] = 0.f;
    __syncthreads();
    int wl = tid >> 5, lane = tid & 31;
    int gw = blockIdx.x * 8 + wl;          // 8192 warps
    int b = gw >> 1, h = gw & 1;
    int ti = __ldg(target + b);
    float4 t4 = ((const float4*)(Wt + (long)ti * E_))[lane];
    const int* cr = contex + b * C_;
    int c0 = h * 25;
    sim_chunk<10>(cr, c0, Wc, lane, b, t4, s_z);
    sim_chunk<10>(cr, c0 + 10, Wc, lane, b, t4, s_z);
    sim_chunk<5>(cr, c0 + 20, Wc, lane, b, t4, s_z);
    __syncthreads();
    if (tid < C_ && s_z[tid] != 0.f) atomicAdd(&g_colsum[tid], s_z[tid]);
}

template<int N>
__device__ __forceinline__ void att_chunk(const int* __restrict__ cr, int c0,
                                          const float* __restrict__ Wc,
                                          int lane, int b, const float* s_inv,
                                          float& ax, float& ay, float& az, float& aw) {
    float4 x[N]; float sc[N];
#pragma unroll
    for (int j = 0; j < N; j++) {
        int ci = __ldg(cr + c0 + j);
        x[j] = ((const float4*)(Wc + (long)ci * E_))[lane];
    }
#pragma unroll
    for (int j = 0; j < N; j++)
        sc[j] = expf(g_sim[(c0 + j) * B_ + b]) * s_inv[c0 + j];
#pragma unroll
    for (int j = 0; j < N; j++) {
        ax += sc[j] * x[j].x; ay += sc[j] * x[j].y;
        az += sc[j] * x[j].z; aw += sc[j] * x[j].w;
    }
}

// attended[b]: 2 warps per b, pairwise combine; accumulate proto & cos
__global__ void k_attend(const int* __restrict__ contex, const float* __restrict__ Wc) {
    __shared__ float s_inv[C_];
    __shared__ float4 s_part[8][32];
    __shared__ float s_acc[E_];
    __shared__ float s_cos;
    int tid = threadIdx.x;
    if (tid < C_) s_inv[tid] = 1.0f / (g_colsum[tid] * DK_);
    if (tid < E_) s_acc[tid] = 0.f;
    if (tid == 0) s_cos = 0.f;
    __syncthreads();
    int wl = tid >> 5, lane = tid & 31;
    int gw = blockIdx.x * 8 + wl;          // 8192 warps
    int b = gw >> 1, h = gw & 1;
    const int* cr = contex + b * C_;
    float ax = 0, ay = 0, az = 0, aw = 0;
    int c0 = h * 25;
    att_chunk<10>(cr, c0, Wc, lane, b, s_inv, ax, ay, az, aw);
    att_chunk<10>(cr, c0 + 10, Wc, lane, b, s_inv, ax, ay, az, aw);
    att_chunk<5>(cr, c0 + 20, Wc, lane, b, s_inv, ax, ay, az, aw);
    s_part[wl][lane] = make_float4(ax, ay, az, aw);
    __syncthreads();
    if ((wl & 1) == 0) {
        float4 p1 = s_part[wl][lane], p2 = s_part[wl + 1][lane];
        ax = p1.x + p2.x; ay = p1.y + p2.y; az = p1.z + p2.z; aw = p1.w + p2.w;
        float4 t4 = ((const float4*)g_t0)[lane];
        float d = ax * t4.x + ay * t4.y + az * t4.z + aw * t4.w;
        float q = ax * ax + ay * ay + az * az + aw * aw;
        d = warp_sum(d); q = warp_sum(q);
        if (lane == 0) {
            float cosb = d / (fmaxf(sqrtf(q), 1e-8f) * fmaxf(g_t0norm, 1e-8f));
            atomicAdd(&s_cos, cosb);
        }
        atomicAdd(&s_acc[lane * 4 + 0], ax);
        atomicAdd(&s_acc[lane * 4 + 1], ay);
        atomicAdd(&s_acc[lane * 4 + 2], az);
        atomicAdd(&s_acc[lane * 4 + 3], aw);
    }
    __syncthreads();
    if (tid < E_) atomicAdd(&g_proto[tid], s_acc[tid]);
    if (tid == 0) atomicAdd(&g_cos_sum, s_cos);
}

// sim_m[m] = dot(proto/B, pm[m]); 8 rows per warp (MLP=8); track global max/min keys
__global__ void k_simm(const float* __restrict__ pm) {
    __shared__ float4 s_proto4[32];
    __shared__ unsigned s_kmax[8], s_kmin[8];
    int tid = threadIdx.x, lane = tid & 31, wl = tid >> 5;
    if (tid < 32) {
        float inv = 1.0f / (float)B_;
        float4 p = ((const float4*)g_proto)[tid];
        s_proto4[tid] = make_float4(p.x * inv, p.y * inv, p.z * inv, p.w * inv);
    }
    __syncthreads();
    float4 p = s_proto4[lane];
    int w = (blockIdx.x * 8 + wl) * 8;     // 3125 blocks * 8 warps * 8 rows = 200000
    float d[8];
#pragma unroll
    for (int r = 0; r < 8; r++) {
        float4 x = ((const float4*)(pm + (long)(w + r) * E_))[lane];
        d[r] = x.x * p.x + x.y * p.y + x.z * p.z + x.w * p.w;
    }
#pragma unroll
    for (int r = 0; r < 8; r++) d[r] = warp_sum(d[r]);
    if (lane == 0) {
        unsigned kx = 0u, kn = 0xFFFFFFFFu;
#pragma unroll
        for (int r = 0; r < 8; r++) {
            g_simm[w + r] = d[r];
            unsigned k = flipkey(d[r]);
            kx = max(kx, k); kn = min(kn, k);
        }
        s_kmax[wl] = kx; s_kmin[wl] = kn;
    }
    __syncthreads();
    if (tid == 0) {
        unsigned kx = s_kmax[0], kn = s_kmin[0];
        for (int i = 1; i < 8; i++) { kx = max(kx, s_kmax[i]); kn = min(kn, s_kmin[i]); }
        atomicMax(&g_maxkey, kx); atomicMin(&g_minkey, kn);
    }
}

// Z sums + qkey materialization + qkey radix pass-0 hist + fused scan (last block)
__global__ void k_expsum() {
    __shared__ unsigned h[256];
    __shared__ float s1[8], s2[8];
    __shared__ bool s_last;
    int tid = threadIdx.x;
    h[tid] = 0u;
    __syncthreads();
    float mx1 = unflip(g_maxkey);
    float mn = unflip(g_minkey);
    float z1 = 0.f, z2 = 0.f;
    int idx = blockIdx.x * blockDim.x + tid, stride = gridDim.x * blockDim.x;
    for (int i = idx; i < M_; i += stride) {
        float s = g_simm[i];
        float q = expf(s - mx1);
        unsigned key = flipkey(q);
        g_qkey[i] = key;
        atomicAdd(&h[key >> 24], 1u);
        z1 += q;
        z2 += expf((mn - s) / DK_);
    }
    z1 = warp_sum(z1); z2 = warp_sum(z2);
    int wl = tid >> 5, lane = tid & 31;
    if (lane == 0) { s1[wl] = z1; s2[wl] = z2; }
    __syncthreads();
    if (tid == 0) {
        float a = 0, b = 0;
        for (int i = 0; i < 8; i++) { a += s1[i]; b += s2[i]; }
        atomicAdd(&g_Z1, a); atomicAdd(&g_Z2, b);
    }
    if (h[tid]) atomicAdd(&g_hist[0][tid], h[tid]);
    __threadfence();
    if (tid == 0) s_last = (atomicAdd(&g_done[0], 1u) == gridDim.x - 1);
    __syncthreads();
    if (!s_last) return;
    __threadfence();
    h[tid] = g_hist[0][tid];
    __syncthreads();
    if (tid == 0) {
        unsigned cum = 0; int krem = g_krem;
        for (int bin = 255; bin >= 0; bin--) {
            unsigned hh = h[bin];
            if (cum + hh >= (unsigned)krem) {
                g_prefix = (unsigned)bin; g_krem = krem - (int)cum;
                break;
            }
            cum += hh;
        }
    }
}

// qkey radix passes 1..3, fused scan (last block)
__global__ void k_qhist(int pass, int shift, int slot) {
    __shared__ unsigned h[256];
    __shared__ bool s_last;
    int tid = threadIdx.x;
    h[tid] = 0u; __syncthreads();
    unsigned pref = g_prefix;
    int idx = blockIdx.x * blockDim.x + tid, stride = gridDim.x * blockDim.x;
    for (int i = idx; i < M_; i += stride) {
        unsigned key = g_qkey[i];
        if ((key >> (shift + 8)) == pref) atomicAdd(&h[(key >> shift) & 255u], 1u);
    }
    __syncthreads();
    if (h[tid]) atomicAdd(&g_hist[pass][tid], h[tid]);
    __threadfence();
    if (tid == 0) s_last = (atomicAdd(&g_done[slot], 1u) == gridDim.x - 1);
    __syncthreads();
    if (!s_last) return;
    __threadfence();
    h[tid] = g_hist[pass][tid];
    __syncthreads();
    if (tid == 0) {
        unsigned cum = 0; int krem = g_krem;
        for (int bin = 255; bin >= 0; bin--) {
            unsigned hh = h[bin];
            if (cum + hh >= (unsigned)krem) {
                g_prefix = (pref << 8) | (unsigned)bin;
                g_krem = krem - (int)cum;
                if (pass == 3) { g_Lkey = (pref << 8) | (unsigned)bin; g_ikrem = krem - (int)cum; }
                break;
            }
            cum += hh;
        }
    }
}

// ascending index-select among ties (2 passes of 9 bits; indices < 2^18), fused scan
__global__ void k_ihist(int pass, int slot) {
    __shared__ unsigned h[512];
    __shared__ bool s_last;
    int tid = threadIdx.x;
    h[tid] = 0u; h[tid + 256] = 0u;
    __syncthreads();
    unsigned L = g_Lkey;
    unsigned b0 = g_iprefix;
    int idx = blockIdx.x * blockDim.x + tid, stride = gridDim.x * blockDim.x;
    for (int i = idx; i < M_; i += stride) {
        if (g_qkey[i] != L) continue;
        unsigned u = (unsigned)i;
        if (pass == 0) atomicAdd(&h[u >> 9], 1u);
        else if ((u >> 9) == b0) atomicAdd(&h[u & 511u], 1u);
    }
    __syncthreads();
    if (h[tid]) atomicAdd(&g_ihist[pass][tid], h[tid]);
    if (h[tid + 256]) atomicAdd(&g_ihist[pass][tid + 256], h[tid + 256]);
    __threadfence();
    if (tid == 0) s_last = (atomicAdd(&g_done[slot], 1u) == gridDim.x - 1);
    __syncthreads();
    if (!s_last) return;
    __threadfence();
    h[tid] = g_ihist[pass][tid];
    h[tid + 256] = g_ihist[pass][tid + 256];
    __syncthreads();
    if (tid == 0) {
        unsigned cum = 0; int krem = g_ikrem;
        for (int bin = 0; bin < 512; bin++) {
            unsigned hh = h[bin];
            if (cum + hh >= (unsigned)krem) {
                if (pass == 0) { g_iprefix = (unsigned)bin; g_ikrem = krem - (int)cum; }
                else g_iprefix = (b0 << 9) | (unsigned)bin;   // final cut index
                break;
            }
            cum += hh;
        }
    }
}

// fused: mem_contex/neg accumulation + output copy + scatter-update (flags inline); 4-deep
// Stores realigned to 16B via lane shuffle when mem_off % 4 == 1 (the actual case).
__global__ void k_update(const float* __restrict__ pm, float* __restrict__ out,
                         int mem_off, const int* __restrict__ repe, int has_repe) {
    __shared__ float4 s_proto4[32];
    __shared__ float s_mem[E_], s_neg[E_];
    int tid = threadIdx.x;
    if (tid < 32) {
        float inv = 1.0f / (float)B_;
        float4 p = ((const float4*)g_proto)[tid];
        s_proto4[tid] = make_float4(p.x * inv, p.y * inv, p.z * inv, p.w * inv);
    }
    if (tid < E_) { s_mem[tid] = 0.f; s_neg[tid] = 0.f; }
    __syncthreads();
    float mx1 = unflip(g_maxkey), mn = unflip(g_minkey);
    float Z1 = g_Z1, Z2 = g_Z2;
    unsigned L = g_Lkey;
    unsigned cut = g_iprefix;
    int rep = has_repe ? repe[0] : 1;
    bool al = ((mem_off & 3) == 1);         // aligned-shift fast path
    int lane = tid & 31, wl = tid >> 5;
    int gw = blockIdx.x * 8 + wl;
    int nw = gridDim.x * 8;
    float4 am = make_float4(0, 0, 0, 0), an = make_float4(0, 0, 0, 0);
    float4 pr = s_proto4[lane];
    float* ob = out + mem_off;
    for (int m0 = gw; m0 < M_; m0 += 4 * nw) {
        float s[4]; float4 v[4]; int mm[4]; int cnt = 0;
#pragma unroll
        for (int rr = 0; rr < 4; rr++) {
            int m = m0 + rr * nw;
            if (m < M_) { mm[cnt] = m; s[cnt] = __ldg(g_simm + m); cnt++; }
        }
#pragma unroll
        for (int rr = 0; rr < 4; rr++)
            if (rr < cnt) v[rr] = ((const float4*)(pm + (long)mm[rr] * E_))[lane];
#pragma unroll
        for (int rr = 0; rr < 4; rr++) {
            if (rr >= cnt) break;
            int m = mm[rr];
            float q = expf(s[rr] - mx1);
            float w1 = q / Z1 / DK_;                     // score_m[m]
            float w2 = expf((mn - s[rr]) / DK_) / Z2;    // score_neg[m]
            float4 vv = v[rr];
            am.x += w1 * vv.x; am.y += w1 * vv.y; am.z += w1 * vv.z; am.w += w1 * vv.w;
            an.x += w2 * vv.x; an.y += w2 * vv.y; an.z += w2 * vv.z; an.w += w2 * vv.w;
            float4 o = vv;
            unsigned key = flipkey(q);
            bool fl = (key > L) || (key == L && (unsigned)m <= cut);
            if (rep && fl) {
                o.x = vv.x + w1 * pr.x; o.y = vv.y + w1 * pr.y;
                o.z = vv.z + w1 * pr.z; o.w = vv.w + w1 * pr.w;
                float ss = o.x * o.x + o.y * o.y + o.z * o.z + o.w * o.w;
                ss = warp_sum(ss);
                float inv2 = 1.0f / fmaxf(sqrtf(ss), 1e-12f);
                o.x *= inv2; o.y *= inv2; o.z *= inv2; o.w *= inv2;
            }
            float* base = ob + (long)m * E_;
            if (al) {
                // realigned 128-bit stores: element 4l+3 starts a 16B-aligned float4
                float nx = __shfl_down_sync(0xffffffffu, o.x, 1);
                float ny = __shfl_down_sync(0xffffffffu, o.y, 1);
                float nz = __shfl_down_sync(0xffffffffu, o.z, 1);
                if (lane == 0) { base[0] = o.x; base[1] = o.y; base[2] = o.z; }
                if (lane < 31) {
                    float4 st = make_float4(o.w, nx, ny, nz);
                    *reinterpret_cast<float4*>(base + lane * 4 + 3) = st;
                } else {
                    base[127] = o.w;
                }
            } else {
                float* wp = base + lane * 4;
                wp[0] = o.x; wp[1] = o.y; wp[2] = o.z; wp[3] = o.w;
            }
        }
    }
    atomicAdd(&s_mem[lane * 4 + 0], am.x); atomicAdd(&s_mem[lane * 4 + 1], am.y);
    atomicAdd(&s_mem[lane * 4 + 2], am.z); atomicAdd(&s_mem[lane * 4 + 3], am.w);
    atomicAdd(&s_neg[lane * 4 + 0], an.x); atomicAdd(&s_neg[lane * 4 + 1], an.y);
    atomicAdd(&s_neg[lane * 4 + 2], an.z); atomicAdd(&s_neg[lane * 4 + 3], an.w);
    __syncthreads();
    if (tid < E_) { atomicAdd(&g_mem[tid], s_mem[tid]); atomicAdd(&g_negmem[tid], s_neg[tid]); }
}

__global__ void k_final(float* __restrict__ out, int mem_off) {
    int tid = threadIdx.x;  // 128 threads
    float p = g_proto[tid] * (1.0f / (float)B_);
    float mm = g_mem[tid], nn = g_negmem[tid], t = g_t0[tid];
    float v[6] = { p * t, p * p, mm * t, mm * mm, nn * t, nn * nn };
#pragma unroll
    for (int k = 0; k < 6; k++)
#pragma unroll
        for (int o = 16; o; o >>= 1) v[k] += __shfl_xor_sync(0xffffffffu, v[k], o);
    __shared__ float sm[4][6];
    int w = tid >> 5, l = tid & 31;
    if (l == 0) for (int k = 0; k < 6; k++) sm[w][k] = v[k];
    __syncthreads();
    if (tid == 0) {
        float r[6];
        for (int k = 0; k < 6; k++) r[k] = sm[0][k] + sm[1][k] + sm[2][k] + sm[3][k];
        float tn = fmaxf(g_t0norm, 1e-8f);
        float cosP = r[0] / (fmaxf(sqrtf(r[1]), 1e-8f) * tn);
        float cosM = r[2] / (fmaxf(sqrtf(r[3]), 1e-8f) * tn);
        float cosN = r[4] / (fmaxf(sqrtf(r[5]), 1e-8f) * tn);
        float conte = (g_cos_sum + cosP + cosM) / (float)(B_ + 2);
        float negl = -cosN;
        float loss = logsig(conte) + logsig(negl);
        if (mem_off > 0) out[0] = -loss;
    }
}

// ---------------- launch ----------------
extern "C" void kernel_launch(void* const* d_in, const int* in_sizes, int n_in,
                              void* d_out, int out_size) {
    const int* target = (const int*)d_in[0];
    const int* contex = (const int*)d_in[1];
    const float* Wt = (const float*)d_in[2];
    const float* Wc = (const float*)d_in[3];
    const float* pm = (const float*)d_in[4];
    const int* repe = (n_in > 5) ? (const int*)d_in[5] : nullptr;
    float* out = (float*)d_out;
    int mem_off = out_size - M_ * E_;
    if (mem_off < 0) mem_off = 0;

    k_init<<<1, 256>>>(target, Wt);
    k_sim<<<1024, 256>>>(target, contex, Wt, Wc);
    k_attend<<<1024, 256>>>(contex, Wc);
    k_simm<<<3125, 256>>>(pm);
    k_expsum<<<256, 256>>>();          // qkey pass 0 hist + scan (slot 0)
    k_qhist<<<256, 256>>>(1, 16, 1);
    k_qhist<<<256, 256>>>(2, 8, 2);
    k_qhist<<<256, 256>>>(3, 0, 3);    // also sets Lkey / ikrem
    k_ihist<<<256, 256>>>(0, 4);
    k_ihist<<<256, 256>>>(1, 5);       // sets final cut index
    k_update<<<1184, 256>>>(pm, out, mem_off, repe, repe != nullptr);
    k_final<<<1, E_>>>(out, mem_off);
}

// round 14
// speedup vs baseline: 1.3989x; 1.1860x over previous
#include <cuda_runtime.h>
#include <math.h>

#define B_ 4096
#define C_ 50
#define E_ 128
#define M_ 200000
#define F_ 512
#define DK_ 11.313708498984760f

// ---------------- scratch (device globals; no allocation allowed) ----------------
__device__ float g_sim[C_ * B_];          // sim[c*B+b]
__device__ float g_colsum[C_];            // Z_c = sum_b exp(sim[b,c])
__device__ float g_t0[E_];
__device__ float g_t0norm;
__device__ float g_proto[E_];             // SUM of attended (scale by 1/B at use)
__device__ float g_cos_sum;
__device__ float g_simm[M_];
__device__ unsigned g_qkey[M_];           // flipped key of expf(s - mx)
__device__ unsigned g_maxkey;
__device__ float g_Z1;                    // sum exp(s - mx1): exact scatter weight
__device__ float g_S1, g_S2;              // sum exp(s), sum exp(-s/DK)
__device__ unsigned g_hist[4][256];       // qkey radix (descending)
__device__ unsigned g_ihist[2][512];      // index radix among ties (ascending, 9-bit)
__device__ unsigned g_prefix;
__device__ int g_krem;
__device__ unsigned g_Lkey;               // boundary q-level key
__device__ unsigned g_iprefix;            // pass0: bin b0; pass1: final cut index
__device__ int g_ikrem;
__device__ unsigned g_done[8];            // last-block tickets
__device__ int g_nflag;
__device__ int g_list[1024];
__device__ float g_mem[E_], g_negmem[E_]; // unnormalized U, V sums

// ---------------- helpers ----------------
__device__ __forceinline__ unsigned flipkey(float f) {
    unsigned u = __float_as_uint(f);
    return (u & 0x80000000u) ? ~u : (u | 0x80000000u);
}
__device__ __forceinline__ float unflip(unsigned k) {
    unsigned u = (k & 0x80000000u) ? (k & 0x7FFFFFFFu) : ~k;
    return __uint_as_float(u);
}
__device__ __forceinline__ float warp_sum(float v) {
#pragma unroll
    for (int o = 16; o; o >>= 1) v += __shfl_xor_sync(0xffffffffu, v, o);
    return v;
}
__device__ __forceinline__ float logsig(float x) {
    return (x >= 0.f) ? -log1pf(expf(-x)) : x - log1pf(expf(x));
}

// ---------------- kernels ----------------
__global__ void k_init(const int* __restrict__ target, const float* __restrict__ Wt) {
    int tid = threadIdx.x;  // 256 threads
    if (tid < E_) { g_proto[tid] = 0.f; g_mem[tid] = 0.f; g_negmem[tid] = 0.f; }
    if (tid < C_) g_colsum[tid] = 0.f;
#pragma unroll
    for (int p = 0; p < 4; p++) g_hist[p][tid] = 0u;
#pragma unroll
    for (int p = 0; p < 2; p++) { g_ihist[p][tid] = 0u; g_ihist[p][tid + 256] = 0u; }
    if (tid < 8) g_done[tid] = 0u;
    if (tid == 0) {
        g_cos_sum = 0.f; g_maxkey = 0u;
        g_Z1 = 0.f; g_S1 = 0.f; g_S2 = 0.f; g_prefix = 0u; g_krem = F_;
        g_iprefix = 0u; g_ikrem = 0; g_nflag = 0;
    }
    int ti = target[0];
    float v = 0.f;
    if (tid < E_) { v = Wt[(long)ti * E_ + tid]; g_t0[tid] = v; }
    __shared__ float sm[256];
    sm[tid] = v * v;
    __syncthreads();
    for (int s = 128; s; s >>= 1) { if (tid < s) sm[tid] += sm[tid + s]; __syncthreads(); }
    if (tid == 0) g_t0norm = sqrtf(sm[0]);
}

// batched gather + dot for k_sim; lane0 also accumulates exp into smem Z bins
template<int N>
__device__ __forceinline__ void sim_chunk(const int* __restrict__ cr, int c0,
                                          const float* __restrict__ Wc,
                                          int lane, int b, float4 t4, float* s_z) {
    float4 x[N];
#pragma unroll
    for (int j = 0; j < N; j++) {
        int ci = __ldg(cr + c0 + j);
        x[j] = ((const float4*)(Wc + (long)ci * E_))[lane];
    }
#pragma unroll
    for (int j = 0; j < N; j++) {
        float p = t4.x * x[j].x + t4.y * x[j].y + t4.z * x[j].z + t4.w * x[j].w;
        p = warp_sum(p);
        if (lane == 0) {
            g_sim[(c0 + j) * B_ + b] = p;
            atomicAdd(&s_z[c0 + j], expf(p));
        }
    }
}

// sim[b,c]: 2 warps per b (25 c's each), MLP=10; fused column Z accumulation
__global__ void k_sim(const int* __restrict__ target, const int* __restrict__ contex,
                      const float* __restrict__ Wt, const float* __restrict__ Wc) {
    __shared__ float s_z[C_];
    int tid = threadIdx.x;
    if (tid < C_) s_z[tid] = 0.f;
    __syncthreads();
    int wl = tid >> 5, lane = tid & 31;
    int gw = blockIdx.x * 8 + wl;          // 8192 warps
    int b = gw >> 1, h = gw & 1;
    int ti = __ldg(target + b);
    float4 t4 = ((const float4*)(Wt + (long)ti * E_))[lane];
    const int* cr = contex + b * C_;
    int c0 = h * 25;
    sim_chunk<10>(cr, c0, Wc, lane, b, t4, s_z);
    sim_chunk<10>(cr, c0 + 10, Wc, lane, b, t4, s_z);
    sim_chunk<5>(cr, c0 + 20, Wc, lane, b, t4, s_z);
    __syncthreads();
    if (tid < C_ && s_z[tid] != 0.f) atomicAdd(&g_colsum[tid], s_z[tid]);
}

template<int N>
__device__ __forceinline__ void att_chunk(const int* __restrict__ cr, int c0,
                                          const float* __restrict__ Wc,
                                          int lane, int b, const float* s_inv,
                                          float& ax, float& ay, float& az, float& aw) {
    float4 x[N]; float sc[N];
#pragma unroll
    for (int j = 0; j < N; j++) {
        int ci = __ldg(cr + c0 + j);
        x[j] = ((const float4*)(Wc + (long)ci * E_))[lane];
    }
#pragma unroll
    for (int j = 0; j < N; j++)
        sc[j] = expf(g_sim[(c0 + j) * B_ + b]) * s_inv[c0 + j];
#pragma unroll
    for (int j = 0; j < N; j++) {
        ax += sc[j] * x[j].x; ay += sc[j] * x[j].y;
        az += sc[j] * x[j].z; aw += sc[j] * x[j].w;
    }
}

// attended[b]: 2 warps per b, pairwise combine; accumulate proto & cos
__global__ void k_attend(const int* __restrict__ contex, const float* __restrict__ Wc) {
    __shared__ float s_inv[C_];
    __shared__ float4 s_part[8][32];
    __shared__ float s_acc[E_];
    __shared__ float s_cos;
    int tid = threadIdx.x;
    if (tid < C_) s_inv[tid] = 1.0f / (g_colsum[tid] * DK_);
    if (tid < E_) s_acc[tid] = 0.f;
    if (tid == 0) s_cos = 0.f;
    __syncthreads();
    int wl = tid >> 5, lane = tid & 31;
    int gw = blockIdx.x * 8 + wl;          // 8192 warps
    int b = gw >> 1, h = gw & 1;
    const int* cr = contex + b * C_;
    float ax = 0, ay = 0, az = 0, aw = 0;
    int c0 = h * 25;
    att_chunk<10>(cr, c0, Wc, lane, b, s_inv, ax, ay, az, aw);
    att_chunk<10>(cr, c0 + 10, Wc, lane, b, s_inv, ax, ay, az, aw);
    att_chunk<5>(cr, c0 + 20, Wc, lane, b, s_inv, ax, ay, az, aw);
    s_part[wl][lane] = make_float4(ax, ay, az, aw);
    __syncthreads();
    if ((wl & 1) == 0) {
        float4 p1 = s_part[wl][lane], p2 = s_part[wl + 1][lane];
        ax = p1.x + p2.x; ay = p1.y + p2.y; az = p1.z + p2.z; aw = p1.w + p2.w;
        float4 t4 = ((const float4*)g_t0)[lane];
        float d = ax * t4.x + ay * t4.y + az * t4.z + aw * t4.w;
        float q = ax * ax + ay * ay + az * az + aw * aw;
        d = warp_sum(d); q = warp_sum(q);
        if (lane == 0) {
            float cosb = d / (fmaxf(sqrtf(q), 1e-8f) * fmaxf(g_t0norm, 1e-8f));
            atomicAdd(&s_cos, cosb);
        }
        atomicAdd(&s_acc[lane * 4 + 0], ax);
        atomicAdd(&s_acc[lane * 4 + 1], ay);
        atomicAdd(&s_acc[lane * 4 + 2], az);
        atomicAdd(&s_acc[lane * 4 + 3], aw);
    }
    __syncthreads();
    if (tid < E_) atomicAdd(&g_proto[tid], s_acc[tid]);
    if (tid == 0) atomicAdd(&g_cos_sum, s_cos);
}

// FUSED: sim_m + unnormalized mem/neg accumulation + output copy.
// Reads pm exactly once; writes copy to out (flagged rows fixed later by k_scatter).
// grid-resident 444 blocks, 4 rows per warp.
__global__ void __launch_bounds__(256) k_simm(const float* __restrict__ pm,
                                              float* __restrict__ out, int mem_off) {
    __shared__ float4 s_proto4[32];
    __shared__ float s_U[E_], s_V[E_];
    __shared__ float s_S[2];
    __shared__ unsigned s_kmax[8];
    int tid = threadIdx.x, lane = tid & 31, wl = tid >> 5;
    if (tid < 32) {
        float inv = 1.0f / (float)B_;
        float4 p = ((const float4*)g_proto)[tid];
        s_proto4[tid] = make_float4(p.x * inv, p.y * inv, p.z * inv, p.w * inv);
    }
    if (tid < E_) { s_U[tid] = 0.f; s_V[tid] = 0.f; }
    if (tid < 2) s_S[tid] = 0.f;
    __syncthreads();
    float4 p = s_proto4[lane];
    float4 U = make_float4(0, 0, 0, 0), V = make_float4(0, 0, 0, 0);
    float S1 = 0.f, S2 = 0.f;
    unsigned kmax = 0u;
    float* ob = out + mem_off;
    const int nchunk = M_ / 4;             // 50000 chunks of 4 rows
    int cstride = gridDim.x * 8;
    for (int chunk = blockIdx.x * 8 + wl; chunk < nchunk; chunk += cstride) {
        int w = chunk * 4;
        float4 x[4]; float d[4];
#pragma unroll
        for (int r = 0; r < 4; r++) {
            x[r] = ((const float4*)(pm + (long)(w + r) * E_))[lane];
            d[r] = x[r].x * p.x + x[r].y * p.y + x[r].z * p.z + x[r].w * p.w;
        }
#pragma unroll
        for (int r = 0; r < 4; r++) d[r] = warp_sum(d[r]);
        if (lane == 0) {
#pragma unroll
            for (int r = 0; r < 4; r++) {
                g_simm[w + r] = d[r];
                kmax = max(kmax, flipkey(d[r]));
            }
        }
#pragma unroll
        for (int r = 0; r < 4; r++) {
            float e1 = expf(d[r]);
            float e2 = expf(-d[r] / DK_);
            U.x += e1 * x[r].x; U.y += e1 * x[r].y; U.z += e1 * x[r].z; U.w += e1 * x[r].w;
            V.x += e2 * x[r].x; V.y += e2 * x[r].y; V.z += e2 * x[r].z; V.w += e2 * x[r].w;
            if (lane == 0) { S1 += e1; S2 += e2; }
            float* base = ob + (long)(w + r) * E_ + lane * 4;  // misaligned base -> scalar stores
            base[0] = x[r].x; base[1] = x[r].y; base[2] = x[r].z; base[3] = x[r].w;
        }
    }
    atomicAdd(&s_U[lane * 4 + 0], U.x); atomicAdd(&s_U[lane * 4 + 1], U.y);
    atomicAdd(&s_U[lane * 4 + 2], U.z); atomicAdd(&s_U[lane * 4 + 3], U.w);
    atomicAdd(&s_V[lane * 4 + 0], V.x); atomicAdd(&s_V[lane * 4 + 1], V.y);
    atomicAdd(&s_V[lane * 4 + 2], V.z); atomicAdd(&s_V[lane * 4 + 3], V.w);
    if (lane == 0) { atomicAdd(&s_S[0], S1); atomicAdd(&s_S[1], S2); s_kmax[wl] = kmax; }
    __syncthreads();
    if (tid < E_) { atomicAdd(&g_mem[tid], s_U[tid]); atomicAdd(&g_negmem[tid], s_V[tid]); }
    if (tid == 0) {
        atomicAdd(&g_S1, s_S[0]); atomicAdd(&g_S2, s_S[1]);
        unsigned kx = s_kmax[0];
        for (int i = 1; i < 8; i++) kx = max(kx, s_kmax[i]);
        atomicMax(&g_maxkey, kx);
    }
}

// Z1 + qkey materialization + qkey radix pass-0 hist + fused scan (last block)
__global__ void k_expsum() {
    __shared__ unsigned h[256];
    __shared__ float s1[8];
    __shared__ bool s_last;
    int tid = threadIdx.x;
    h[tid] = 0u;
    __syncthreads();
    float mx1 = unflip(g_maxkey);
    float z1 = 0.f;
    int idx = blockIdx.x * blockDim.x + tid, stride = gridDim.x * blockDim.x;
    for (int i = idx; i < M_; i += stride) {
        float s = g_simm[i];
        float q = expf(s - mx1);
        unsigned key = flipkey(q);
        g_qkey[i] = key;
        atomicAdd(&h[key >> 24], 1u);
        z1 += q;
    }
    z1 = warp_sum(z1);
    int wl = tid >> 5, lane = tid & 31;
    if (lane == 0) s1[wl] = z1;
    __syncthreads();
    if (tid == 0) {
        float a = 0;
        for (int i = 0; i < 8; i++) a += s1[i];
        atomicAdd(&g_Z1, a);
    }
    if (h[tid]) atomicAdd(&g_hist[0][tid], h[tid]);
    __threadfence();
    if (tid == 0) s_last = (atomicAdd(&g_done[0], 1u) == gridDim.x - 1);
    __syncthreads();
    if (!s_last) return;
    __threadfence();
    h[tid] = g_hist[0][tid];
    __syncthreads();
    if (tid == 0) {
        unsigned cum = 0; int krem = g_krem;
        for (int bin = 255; bin >= 0; bin--) {
            unsigned hh = h[bin];
            if (cum + hh >= (unsigned)krem) {
                g_prefix = (unsigned)bin; g_krem = krem - (int)cum;
                break;
            }
            cum += hh;
        }
    }
}

// qkey radix passes 1..3, fused scan (last block)
__global__ void k_qhist(int pass, int shift, int slot) {
    __shared__ unsigned h[256];
    __shared__ bool s_last;
    int tid = threadIdx.x;
    h[tid] = 0u; __syncthreads();
    unsigned pref = g_prefix;
    int idx = blockIdx.x * blockDim.x + tid, stride = gridDim.x * blockDim.x;
    for (int i = idx; i < M_; i += stride) {
        unsigned key = g_qkey[i];
        if ((key >> (shift + 8)) == pref) atomicAdd(&h[(key >> shift) & 255u], 1u);
    }
    __syncthreads();
    if (h[tid]) atomicAdd(&g_hist[pass][tid], h[tid]);
    __threadfence();
    if (tid == 0) s_last = (atomicAdd(&g_done[slot], 1u) == gridDim.x - 1);
    __syncthreads();
    if (!s_last) return;
    __threadfence();
    h[tid] = g_hist[pass][tid];
    __syncthreads();
    if (tid == 0) {
        unsigned cum = 0; int krem = g_krem;
        for (int bin = 255; bin >= 0; bin--) {
            unsigned hh = h[bin];
            if (cum + hh >= (unsigned)krem) {
                g_prefix = (pref << 8) | (unsigned)bin;
                g_krem = krem - (int)cum;
                if (pass == 3) { g_Lkey = (pref << 8) | (unsigned)bin; g_ikrem = krem - (int)cum; }
                break;
            }
            cum += hh;
        }
    }
}

// ascending index-select among ties (2 passes of 9 bits; indices < 2^18), fused scan
__global__ void k_ihist(int pass, int slot) {
    __shared__ unsigned h[512];
    __shared__ bool s_last;
    int tid = threadIdx.x;
    h[tid] = 0u; h[tid + 256] = 0u;
    __syncthreads();
    unsigned L = g_Lkey;
    unsigned b0 = g_iprefix;
    int idx = blockIdx.x * blockDim.x + tid, stride = gridDim.x * blockDim.x;
    for (int i = idx; i < M_; i += stride) {
        if (g_qkey[i] != L) continue;
        unsigned u = (unsigned)i;
        if (pass == 0) atomicAdd(&h[u >> 9], 1u);
        else if ((u >> 9) == b0) atomicAdd(&h[u & 511u], 1u);
    }
    __syncthreads();
    if (h[tid]) atomicAdd(&g_ihist[pass][tid], h[tid]);
    if (h[tid + 256]) atomicAdd(&g_ihist[pass][tid + 256], h[tid + 256]);
    __threadfence();
    if (tid == 0) s_last = (atomicAdd(&g_done[slot], 1u) == gridDim.x - 1);
    __syncthreads();
    if (!s_last) return;
    __threadfence();
    h[tid] = g_ihist[pass][tid];
    h[tid + 256] = g_ihist[pass][tid + 256];
    __syncthreads();
    if (tid == 0) {
        unsigned cum = 0; int krem = g_ikrem;
        for (int bin = 0; bin < 512; bin++) {
            unsigned hh = h[bin];
            if (cum + hh >= (unsigned)krem) {
                if (pass == 0) { g_iprefix = (unsigned)bin; g_ikrem = krem - (int)cum; }
                else g_iprefix = (b0 << 9) | (unsigned)bin;   // final cut index
                break;
            }
            cum += hh;
        }
    }
}

// build the flagged-row list (set identical to reference top-512)
__global__ void k_flagscan() {
    unsigned L = g_Lkey, cut = g_iprefix;
    int idx = blockIdx.x * blockDim.x + threadIdx.x, stride = gridDim.x * blockDim.x;
    for (int i = idx; i < M_; i += stride) {
        unsigned key = g_qkey[i];
        if (key > L || (key == L && (unsigned)i <= cut)) {
            int p = atomicAdd(&g_nflag, 1);
            if (p < 1024) g_list[p] = i;
        }
    }
}

// rewrite the flagged rows (copy already written by k_simm); exact reference formula
__global__ void k_scatter(const float* __restrict__ pm, float* __restrict__ out,
                          int mem_off, const int* __restrict__ repe, int has_repe) {
    int rep = has_repe ? repe[0] : 1;
    if (!rep) return;
    int tid = threadIdx.x, lane = tid & 31, wl = tid >> 5;
    int gw = blockIdx.x * 8 + wl;          // 64 blocks * 8 = 512 warps
    int n = g_nflag; if (n > 1024) n = 1024;
    if (gw >= n) return;
    int m = g_list[gw];
    float mx1 = unflip(g_maxkey);
    float s = g_simm[m];
    float q = expf(s - mx1);
    float w1 = q / g_Z1 / DK_;             // exact reference score_m[m]
    float inv = 1.0f / (float)B_;
    float4 p = ((const float4*)g_proto)[lane];
    float4 pr = make_float4(p.x * inv, p.y * inv, p.z * inv, p.w * inv);
    float4 v = ((const float4*)(pm + (long)m * E_))[lane];
    float4 o;
    o.x = v.x + w1 * pr.x; o.y = v.y + w1 * pr.y;
    o.z = v.z + w1 * pr.z; o.w = v.w + w1 * pr.w;
    float ss = o.x * o.x + o.y * o.y + o.z * o.z + o.w * o.w;
    ss = warp_sum(ss);
    float inv2 = 1.0f / fmaxf(sqrtf(ss), 1e-12f);
    float* wp = out + mem_off + (long)m * E_ + lane * 4;
    wp[0] = o.x * inv2; wp[1] = o.y * inv2; wp[2] = o.z * inv2; wp[3] = o.w * inv2;
}

__global__ void k_final(float* __restrict__ out, int mem_off) {
    int tid = threadIdx.x;  // 128 threads
    float p = g_proto[tid] * (1.0f / (float)B_);
    float mm = g_mem[tid] / (g_S1 * DK_);       // mem_contex
    float nn = g_negmem[tid] / g_S2;            // neg_mem_contex
    float t = g_t0[tid];
    float v[6] = { p * t, p * p, mm * t, mm * mm, nn * t, nn * nn };
#pragma unroll
    for (int k = 0; k < 6; k++)
#pragma unroll
        for (int o = 16; o; o >>= 1) v[k] += __shfl_xor_sync(0xffffffffu, v[k], o);
    __shared__ float sm[4][6];
    int w = tid >> 5, l = tid & 31;
    if (l == 0) for (int k = 0; k < 6; k++) sm[w][k] = v[k];
    __syncthreads();
    if (tid == 0) {
        float r[6];
        for (int k = 0; k < 6; k++) r[k] = sm[0][k] + sm[1][k] + sm[2][k] + sm[3][k];
        float tn = fmaxf(g_t0norm, 1e-8f);
        float cosP = r[0] / (fmaxf(sqrtf(r[1]), 1e-8f) * tn);
        float cosM = r[2] / (fmaxf(sqrtf(r[3]), 1e-8f) * tn);
        float cosN = r[4] / (fmaxf(sqrtf(r[5]), 1e-8f) * tn);
        float conte = (g_cos_sum + cosP + cosM) / (float)(B_ + 2);
        float negl = -cosN;
        float loss = logsig(conte) + logsig(negl);
        if (mem_off > 0) out[0] = -loss;
    }
}

// ---------------- launch ----------------
extern "C" void kernel_launch(void* const* d_in, const int* in_sizes, int n_in,
                              void* d_out, int out_size) {
    const int* target = (const int*)d_in[0];
    const int* contex = (const int*)d_in[1];
    const float* Wt = (const float*)d_in[2];
    const float* Wc = (const float*)d_in[3];
    const float* pm = (const float*)d_in[4];
    const int* repe = (n_in > 5) ? (const int*)d_in[5] : nullptr;
    float* out = (float*)d_out;
    int mem_off = out_size - M_ * E_;
    if (mem_off < 0) mem_off = 0;

    k_init<<<1, 256>>>(target, Wt);
    k_sim<<<1024, 256>>>(target, contex, Wt, Wc);
    k_attend<<<1024, 256>>>(contex, Wc);
    k_simm<<<444, 256>>>(pm, out, mem_off);   // fused dot + U/V + output copy
    k_expsum<<<256, 256>>>();          // qkey pass 0 hist + scan (slot 0)
    k_qhist<<<256, 256>>>(1, 16, 1);
    k_qhist<<<256, 256>>>(2, 8, 2);
    k_qhist<<<256, 256>>>(3, 0, 3);    // also sets Lkey / ikrem
    k_ihist<<<256, 256>>>(0, 4);
    k_ihist<<<256, 256>>>(1, 5);       // sets final cut index
    k_flagscan<<<256, 256>>>();
    k_scatter<<<64, 256>>>(pm, out, mem_off, repe, repe != nullptr);
    k_final<<<1, E_>>>(out, mem_off);
}